// round 15
// baseline (speedup 1.0000x reference)
#include <cuda_runtime.h>
#include <cstdint>
#include <math.h>

// LSTM cell B=8192, I=H=1024, mma.sync.m16n8k8 tf32.
// Round 15: 512-thread CTA (16 warps 4Mx4N), BNH=64, KT=64, 2-stage double
// buffer (2x96KB smem), 32 stages -> half the barrier count. Gate-paired gB,
// MUFU epilogue, merged prepass (layouts unchanged from R14).

#define BATCH  8192
#define HDIM   1024
#define NSTAGE 32
#define STAGE_WORDS 24576                   // 96KB: A 32KB + B 64KB
#define OFF_BIAS (2 * STAGE_WORDS)
#define SMEM_BYTES ((OFF_BIAS + 256) * 4)   // 197632

// Fragment-major tf32 scratch (same as R14).
// gA: [RT=512][kt=256][lane=32][4 words]
// gB (gate-paired): [gp=2][NT=128][kt=256][lane=32][4 words]
__device__ __align__(128) uint32_t gA[16777216];   // 64MB
__device__ __align__(128) uint32_t gB[8388608];    // 32MB

__device__ __forceinline__ uint32_t cvt_tf32(float v) {
    uint32_t u; asm("cvt.rna.tf32.f32 %0, %1;" : "=r"(u) : "f"(v)); return u;
}
__device__ __forceinline__ float tanh_ap(float x) {
    float y; asm("tanh.approx.f32 %0, %1;" : "=f"(y) : "f"(x)); return y;
}
__device__ __forceinline__ float sig_ap(float x) {
    return fmaf(0.5f, tanh_ap(0.5f * x), 0.5f);
}

__device__ __forceinline__ uint32_t smem_u32(const void* p) {
    uint32_t a;
    asm("{ .reg .u64 t; cvta.to.shared.u64 t, %1; cvt.u32.u64 %0, t; }" : "=r"(a) : "l"(p));
    return a;
}
__device__ __forceinline__ void cpa16(uint32_t sdst, const void* gsrc) {
    asm volatile("cp.async.cg.shared.global [%0], [%1], 16;" :: "r"(sdst), "l"(gsrc) : "memory");
}
__device__ __forceinline__ void mma8(float* c,
                                     uint32_t a0, uint32_t a1, uint32_t a2, uint32_t a3,
                                     uint32_t b0, uint32_t b1) {
    asm volatile("mma.sync.aligned.m16n8k8.row.col.f32.tf32.tf32.f32 "
                 "{%0,%1,%2,%3}, {%4,%5,%6,%7}, {%8,%9}, {%0,%1,%2,%3};"
                 : "+f"(c[0]), "+f"(c[1]), "+f"(c[2]), "+f"(c[3])
                 : "r"(a0), "r"(a1), "r"(a2), "r"(a3), "r"(b0), "r"(b1));
}

// ---------------- merged prepass (unchanged from R14) ----------------
__global__ void __launch_bounds__(256)
prep_kernel(const float* __restrict__ x, const float* __restrict__ h,
            const float* __restrict__ wf_i, const float* __restrict__ wf_h,
            const float* __restrict__ wi_i, const float* __restrict__ wi_h,
            const float* __restrict__ wg_i, const float* __restrict__ wg_h,
            const float* __restrict__ wo_i, const float* __restrict__ wo_h)
{
    if (blockIdx.x < 16384) {
        const uint32_t cid  = blockIdx.x * 256u + threadIdx.x;
        const uint32_t lane = cid & 31u;
        const uint32_t kt   = (cid >> 5) & 255u;
        const uint32_t RT   = cid >> 13;
        const uint32_t r0   = RT * 16u + (lane >> 2);
        const uint32_t c0   = kt * 8u + (lane & 3u);
        const float* s = (c0 < 1024u) ? x : h;
        const uint32_t cc = c0 & 1023u;
        uint4 o;
        o.x = cvt_tf32(s[(size_t)r0 * 1024 + cc]);
        o.y = cvt_tf32(s[(size_t)(r0 + 8) * 1024 + cc]);
        o.z = cvt_tf32(s[(size_t)r0 * 1024 + cc + 4]);
        o.w = cvt_tf32(s[(size_t)(r0 + 8) * 1024 + cc + 4]);
        *reinterpret_cast<uint4*>(&gA[(size_t)cid * 4]) = o;
    } else {
        const uint32_t cb   = (blockIdx.x - 16384u) * 256u + threadIdx.x;
        const uint32_t lane = cb & 31u;
        const uint32_t kt   = (cb >> 5) & 255u;
        const uint32_t NT   = (cb >> 13) & 127u;
        const uint32_t gp   = cb >> 20;
        const uint32_t n    = NT * 8u + (lane >> 2);
        const uint32_t k    = kt * 8u + (lane & 3u);
        const float* w0 = (gp == 0) ? ((k < 1024u) ? wf_i : wf_h)
                                    : ((k < 1024u) ? wg_i : wg_h);
        const float* w1 = (gp == 0) ? ((k < 1024u) ? wi_i : wi_h)
                                    : ((k < 1024u) ? wo_i : wo_h);
        const uint32_t kk = k & 1023u;
        uint4 o;
        o.x = cvt_tf32(w0[(size_t)n * 1024 + kk]);
        o.y = cvt_tf32(w0[(size_t)n * 1024 + kk + 4]);
        o.z = cvt_tf32(w1[(size_t)n * 1024 + kk]);
        o.w = cvt_tf32(w1[(size_t)n * 1024 + kk + 4]);
        *reinterpret_cast<uint4*>(&gB[(size_t)cb * 4]) = o;
    }
}

// ---------------- main kernel ----------------
__global__ void __launch_bounds__(512, 1)
lstm_main(const float* __restrict__ c,
          const float* __restrict__ bf_i, const float* __restrict__ bf_h,
          const float* __restrict__ bi_i, const float* __restrict__ bi_h,
          const float* __restrict__ bg_i, const float* __restrict__ bg_h,
          const float* __restrict__ bo_i, const float* __restrict__ bo_h,
          float* __restrict__ out)
{
    extern __shared__ __align__(16) uint32_t smw[];
    const uint32_t sb = smem_u32(smw);
    const int tid = threadIdx.x;
    const int lid = tid & 31;
    const int wid = tid >> 5;
    const int warpM = wid & 3;      // 4 warps in M (32 rows each)
    const int warpN = wid >> 2;     // 4 warps in N (16 cols each)
    const int nb = blockIdx.x;      // 0..15 hidden blocks of 64
    const int mb = blockIdx.y;      // 0..63 batch blocks of 128

    if (tid < 256) {
        const float* bi_tab[4] = {bf_i, bi_i, bg_i, bo_i};
        const float* bh_tab[4] = {bf_h, bi_h, bg_h, bo_h};
        const int g = tid >> 6, j = tid & 63;
        ((float*)(smw + OFF_BIAS))[g * 64 + j] =
            bi_tab[g][nb * 64 + j] + bh_tab[g][nb * 64 + j];
    }

    // ---- cp.async addressing ----
    // A: chunk ca = tid + 512*i (i 0..3): lane=ca&31, kt_l=(ca>>5)&7, RT_l=ca>>8
    const char* aSrcB = (const char*)gA +
        (size_t)((((uint32_t)mb * 8u + ((uint32_t)tid >> 8)) * 256u +
                  (((uint32_t)tid >> 5) & 7u)) * 512u) + ((uint32_t)tid & 31u) * 16u;
    const uint32_t aDstOff = ((uint32_t)tid >> 8) * 4096u +
                             (((uint32_t)tid >> 5) & 7u) * 512u + ((uint32_t)tid & 31u) * 16u;
    // B: chunk cb = tid + 512*i (i 0..7): i&3 -> ntl(+2), i>>2 -> gp
    const char* bSrcB = (const char*)gB +
        (size_t)((((uint32_t)nb * 8u + ((uint32_t)tid >> 8)) * 256u +
                  (((uint32_t)tid >> 5) & 7u)) * 512u) + ((uint32_t)tid & 31u) * 16u;
    const uint32_t bDstOff = 32768u + ((uint32_t)tid >> 8) * 4096u +
                             (((uint32_t)tid >> 5) & 7u) * 512u + ((uint32_t)tid & 31u) * 16u;

#define ISSUE(BUF_)                                                           \
    do {                                                                      \
        const uint32_t da_ = sb + (BUF_) * 98304u + aDstOff;                  \
        const uint32_t db_ = sb + (BUF_) * 98304u + bDstOff;                  \
        cpa16(da_,          aSrcB);                                           \
        cpa16(da_ + 8192u,  aSrcB + 262144);                                  \
        cpa16(da_ + 16384u, aSrcB + 524288);                                  \
        cpa16(da_ + 24576u, aSrcB + 786432);                                  \
        cpa16(db_,          bSrcB);                                           \
        cpa16(db_ + 8192u,  bSrcB + 262144);                                  \
        cpa16(db_ + 16384u, bSrcB + 524288);                                  \
        cpa16(db_ + 24576u, bSrcB + 786432);                                  \
        cpa16(db_ + 32768u, bSrcB + 16777216);                                \
        cpa16(db_ + 40960u, bSrcB + 17039360);                                \
        cpa16(db_ + 49152u, bSrcB + 17301504);                                \
        cpa16(db_ + 57344u, bSrcB + 17563648);                                \
        asm volatile("cp.async.commit_group;" ::: "memory");                  \
        aSrcB += 4096;                                                        \
        bSrcB += 4096;                                                        \
    } while (0)

    float acc[4][2][2][4];
#pragma unroll
    for (int g = 0; g < 4; g++)
#pragma unroll
        for (int mt = 0; mt < 2; mt++)
#pragma unroll
            for (int nt = 0; nt < 2; nt++)
#pragma unroll
                for (int e = 0; e < 4; e++) acc[g][mt][nt][e] = 0.0f;

    // A frag: stage + (warpM*2+mt)*1024 + ks*128 + lid*4
    // B frag: stage + 8192 + gp*8192 + (warpN*2+nt)*1024 + ks*128 + lid*4
#define MMA_BLOCK(BUF_)                                                       \
    do {                                                                      \
        const uint32_t* Ap_ = smw + (BUF_) * STAGE_WORDS + warpM * 2048 + lid * 4; \
        const uint32_t* Bp_ = smw + (BUF_) * STAGE_WORDS + 8192 + warpN * 2048 + lid * 4; \
        _Pragma("unroll")                                                     \
        for (int ks_ = 0; ks_ < 8; ks_++) {                                   \
            const uint4 a0_ = *reinterpret_cast<const uint4*>(Ap_ + ks_ * 128);        \
            const uint4 a1_ = *reinterpret_cast<const uint4*>(Ap_ + 1024 + ks_ * 128); \
            _Pragma("unroll")                                                 \
            for (int nt_ = 0; nt_ < 2; nt_++) {                               \
                const uint4 b01_ = *reinterpret_cast<const uint4*>(           \
                    Bp_ + nt_ * 1024 + ks_ * 128);                            \
                const uint4 b23_ = *reinterpret_cast<const uint4*>(           \
                    Bp_ + 8192 + nt_ * 1024 + ks_ * 128);                     \
                mma8(acc[0][0][nt_], a0_.x, a0_.y, a0_.z, a0_.w, b01_.x, b01_.y); \
                mma8(acc[0][1][nt_], a1_.x, a1_.y, a1_.z, a1_.w, b01_.x, b01_.y); \
                mma8(acc[1][0][nt_], a0_.x, a0_.y, a0_.z, a0_.w, b01_.z, b01_.w); \
                mma8(acc[1][1][nt_], a1_.x, a1_.y, a1_.z, a1_.w, b01_.z, b01_.w); \
                mma8(acc[2][0][nt_], a0_.x, a0_.y, a0_.z, a0_.w, b23_.x, b23_.y); \
                mma8(acc[2][1][nt_], a1_.x, a1_.y, a1_.z, a1_.w, b23_.x, b23_.y); \
                mma8(acc[3][0][nt_], a0_.x, a0_.y, a0_.z, a0_.w, b23_.z, b23_.w); \
                mma8(acc[3][1][nt_], a1_.x, a1_.y, a1_.z, a1_.w, b23_.z, b23_.w); \
            }                                                                 \
        }                                                                     \
    } while (0)

    ISSUE(0);

#pragma unroll 2
    for (int s = 0; s < NSTAGE; s++) {
        asm volatile("cp.async.wait_group 0;" ::: "memory");
        __syncthreads();
        if (s + 1 < NSTAGE) ISSUE((s + 1) & 1);
        if (s & 1) MMA_BLOCK(1); else MMA_BLOCK(0);
    }

    // ---- fused LSTM epilogue (MUFU) ----
    const int gid = lid >> 2;
    const int tig = lid & 3;
    const float* bias_s = (const float*)(smw + OFF_BIAS);
    float* outH = out;
    float* outC = out + (size_t)BATCH * HDIM;
    const int mblk = mb * 128;
    const int nblk = nb * 64;

#pragma unroll
    for (int nt = 0; nt < 2; nt++) {
        const int colloc = warpN * 16 + nt * 8 + tig * 2;
        const float bF0 = bias_s[0 * 64 + colloc], bF1 = bias_s[0 * 64 + colloc + 1];
        const float bI0 = bias_s[1 * 64 + colloc], bI1 = bias_s[1 * 64 + colloc + 1];
        const float bG0 = bias_s[2 * 64 + colloc], bG1 = bias_s[2 * 64 + colloc + 1];
        const float bO0 = bias_s[3 * 64 + colloc], bO1 = bias_s[3 * 64 + colloc + 1];
#pragma unroll
        for (int mt = 0; mt < 2; mt++)
#pragma unroll
            for (int p = 0; p < 2; p++) {
                const int m = mblk + warpM * 32 + mt * 16 + gid + 8 * p;
                const size_t base = (size_t)m * HDIM + nblk + colloc;
                const float2 cc = *(const float2*)&c[base];
                const int e = p * 2;
                const float pf0 = acc[0][mt][nt][e] + bF0, pf1 = acc[0][mt][nt][e + 1] + bF1;
                const float pi0 = acc[1][mt][nt][e] + bI0, pi1 = acc[1][mt][nt][e + 1] + bI1;
                const float pg0 = acc[2][mt][nt][e] + bG0, pg1 = acc[2][mt][nt][e + 1] + bG1;
                const float po0 = acc[3][mt][nt][e] + bO0, po1 = acc[3][mt][nt][e + 1] + bO1;
                const float f0 = sig_ap(pf0), f1 = sig_ap(pf1);
                const float i0 = sig_ap(pi0), i1 = sig_ap(pi1);
                const float g0 = tanh_ap(pg0), g1 = tanh_ap(pg1);
                const float o0 = sig_ap(po0), o1 = sig_ap(po1);
                const float cn0 = fmaf(f0, cc.x, i0 * g0);
                const float cn1 = fmaf(f1, cc.y, i1 * g1);
                *(float2*)&outH[base] = make_float2(o0 * tanh_ap(cn0), o1 * tanh_ap(cn1));
                *(float2*)&outC[base] = make_float2(cn0, cn1);
            }
    }
}

extern "C" void kernel_launch(void* const* d_in, const int* in_sizes, int n_in,
                              void* d_out, int out_size)
{
    const float* x    = (const float*)d_in[0];
    const float* h    = (const float*)d_in[1];
    const float* c    = (const float*)d_in[2];
    const float* wf_i = (const float*)d_in[3];
    const float* bf_i = (const float*)d_in[4];
    const float* wf_h = (const float*)d_in[5];
    const float* bf_h = (const float*)d_in[6];
    const float* wi_i = (const float*)d_in[7];
    const float* bi_i = (const float*)d_in[8];
    const float* wi_h = (const float*)d_in[9];
    const float* bi_h = (const float*)d_in[10];
    const float* wg_i = (const float*)d_in[11];
    const float* bg_i = (const float*)d_in[12];
    const float* wg_h = (const float*)d_in[13];
    const float* bg_h = (const float*)d_in[14];
    const float* wo_i = (const float*)d_in[15];
    const float* bo_i = (const float*)d_in[16];
    const float* wo_h = (const float*)d_in[17];
    const float* bo_h = (const float*)d_in[18];
    float* out = (float*)d_out;

    cudaFuncSetAttribute(lstm_main, cudaFuncAttributeMaxDynamicSharedMemorySize, SMEM_BYTES);

    prep_kernel<<<24576, 256>>>(x, h, wf_i, wf_h, wi_i, wi_h, wg_i, wg_h, wo_i, wo_h);

    dim3 grid(HDIM / 64, BATCH / 128);   // (16, 64)
    lstm_main<<<grid, 512, SMEM_BYTES>>>(c,
                                         bf_i, bf_h, bi_i, bi_h,
                                         bg_i, bg_h, bo_i, bo_h,
                                         out);
}

// round 17
// speedup vs baseline: 1.7257x; 1.7257x over previous
#include <cuda_runtime.h>
#include <cstdint>
#include <math.h>

// LSTM cell B=8192, I=H=1024, mma.sync.m16n8k8 tf32.
// Round 16: R14 baseline (best: 573us) + c-tile cp.async prefetch into the
// retired buf1 during the last stage triple; epilogue reads c from smem.
// 2 CTAs/SM, 3-stage pipeline, gate-paired gB, MUFU epilogue.

#define BATCH  8192
#define HDIM   1024
#define NSTAGE 64
#define STAGE_WORDS 8192                    // 32KB per stage (A 16KB + B 16KB)
#define SMEM_WORDS  (3 * STAGE_WORDS + 128)
#define SMEM_BYTES  (SMEM_WORDS * 4)        // 98816
#define CBUF_BASE   STAGE_WORDS             // c tile parked in buf1 (words)
#define CROW 36                             // c tile row stride (words, 16B-aligned)

// Fragment-major tf32 scratch.
// gA: [RT=512][kt=256][lane=32][4 words]
// gB (gate-paired): [gp=2][NT=128][kt=256][lane=32][4 words]:
//   w0=(g=2gp, k) w1=(g=2gp, k+4) w2=(g=2gp+1, k) w3=(g=2gp+1, k+4)
__device__ __align__(128) uint32_t gA[16777216];   // 64MB
__device__ __align__(128) uint32_t gB[8388608];    // 32MB

__device__ __forceinline__ uint32_t cvt_tf32(float v) {
    uint32_t u; asm("cvt.rna.tf32.f32 %0, %1;" : "=r"(u) : "f"(v)); return u;
}
__device__ __forceinline__ float tanh_ap(float x) {
    float y; asm("tanh.approx.f32 %0, %1;" : "=f"(y) : "f"(x)); return y;
}
__device__ __forceinline__ float sig_ap(float x) {
    return fmaf(0.5f, tanh_ap(0.5f * x), 0.5f);
}

__device__ __forceinline__ uint32_t smem_u32(const void* p) {
    uint32_t a;
    asm("{ .reg .u64 t; cvta.to.shared.u64 t, %1; cvt.u32.u64 %0, t; }" : "=r"(a) : "l"(p));
    return a;
}
__device__ __forceinline__ void cpa16(uint32_t sdst, const void* gsrc) {
    asm volatile("cp.async.cg.shared.global [%0], [%1], 16;" :: "r"(sdst), "l"(gsrc) : "memory");
}
__device__ __forceinline__ void mma8(float* c,
                                     uint32_t a0, uint32_t a1, uint32_t a2, uint32_t a3,
                                     uint32_t b0, uint32_t b1) {
    asm volatile("mma.sync.aligned.m16n8k8.row.col.f32.tf32.tf32.f32 "
                 "{%0,%1,%2,%3}, {%4,%5,%6,%7}, {%8,%9}, {%0,%1,%2,%3};"
                 : "+f"(c[0]), "+f"(c[1]), "+f"(c[2]), "+f"(c[3])
                 : "r"(a0), "r"(a1), "r"(a2), "r"(a3), "r"(b0), "r"(b1));
}

// ---------------- merged prepass (unchanged from R14) ----------------
__global__ void __launch_bounds__(256)
prep_kernel(const float* __restrict__ x, const float* __restrict__ h,
            const float* __restrict__ wf_i, const float* __restrict__ wf_h,
            const float* __restrict__ wi_i, const float* __restrict__ wi_h,
            const float* __restrict__ wg_i, const float* __restrict__ wg_h,
            const float* __restrict__ wo_i, const float* __restrict__ wo_h)
{
    if (blockIdx.x < 16384) {
        const uint32_t cid  = blockIdx.x * 256u + threadIdx.x;
        const uint32_t lane = cid & 31u;
        const uint32_t kt   = (cid >> 5) & 255u;
        const uint32_t RT   = cid >> 13;
        const uint32_t r0   = RT * 16u + (lane >> 2);
        const uint32_t c0   = kt * 8u + (lane & 3u);
        const float* s = (c0 < 1024u) ? x : h;
        const uint32_t cc = c0 & 1023u;
        uint4 o;
        o.x = cvt_tf32(s[(size_t)r0 * 1024 + cc]);
        o.y = cvt_tf32(s[(size_t)(r0 + 8) * 1024 + cc]);
        o.z = cvt_tf32(s[(size_t)r0 * 1024 + cc + 4]);
        o.w = cvt_tf32(s[(size_t)(r0 + 8) * 1024 + cc + 4]);
        *reinterpret_cast<uint4*>(&gA[(size_t)cid * 4]) = o;
    } else {
        const uint32_t cb   = (blockIdx.x - 16384u) * 256u + threadIdx.x;
        const uint32_t lane = cb & 31u;
        const uint32_t kt   = (cb >> 5) & 255u;
        const uint32_t NT   = (cb >> 13) & 127u;
        const uint32_t gp   = cb >> 20;
        const uint32_t n    = NT * 8u + (lane >> 2);
        const uint32_t k    = kt * 8u + (lane & 3u);
        const float* w0 = (gp == 0) ? ((k < 1024u) ? wf_i : wf_h)
                                    : ((k < 1024u) ? wg_i : wg_h);
        const float* w1 = (gp == 0) ? ((k < 1024u) ? wi_i : wi_h)
                                    : ((k < 1024u) ? wo_i : wo_h);
        const uint32_t kk = k & 1023u;
        uint4 o;
        o.x = cvt_tf32(w0[(size_t)n * 1024 + kk]);
        o.y = cvt_tf32(w0[(size_t)n * 1024 + kk + 4]);
        o.z = cvt_tf32(w1[(size_t)n * 1024 + kk]);
        o.w = cvt_tf32(w1[(size_t)n * 1024 + kk + 4]);
        *reinterpret_cast<uint4*>(&gB[(size_t)cb * 4]) = o;
    }
}

// ---------------- main kernel ----------------
__global__ void __launch_bounds__(256, 2)
lstm_main(const float* __restrict__ c,
          const float* __restrict__ bf_i, const float* __restrict__ bf_h,
          const float* __restrict__ bi_i, const float* __restrict__ bi_h,
          const float* __restrict__ bg_i, const float* __restrict__ bg_h,
          const float* __restrict__ bo_i, const float* __restrict__ bo_h,
          float* __restrict__ out)
{
    extern __shared__ __align__(16) uint32_t smw[];
    const uint32_t sb = smem_u32(smw);
    const int tid = threadIdx.x;
    const int lid = tid & 31;
    const int wid = tid >> 5;
    const int warpM = wid & 3;
    const int warpN = wid >> 2;
    const int nb = blockIdx.x;     // 0..31 hidden blocks of 32
    const int mb = blockIdx.y;     // 0..63 batch blocks of 128

    if (tid < 128) {
        const float* bi_tab[4] = {bf_i, bi_i, bg_i, bo_i};
        const float* bh_tab[4] = {bf_h, bi_h, bg_h, bo_h};
        const int g = tid >> 5, j = tid & 31;
        ((float*)(smw + 3 * STAGE_WORDS))[g * 32 + j] =
            bi_tab[g][nb * 32 + j] + bh_tab[g][nb * 32 + j];
    }

    // ---- cp.async addressing (2 base pointers + immediate chunk strides) ----
    const uint32_t t0 = (uint32_t)tid >> 5;
    const char* aSrcB = (const char*)gA +
        (size_t)((((uint32_t)mb * 8u + (t0 >> 2)) * 256u + (t0 & 3u)) * 128u +
                 ((uint32_t)tid & 31u) * 4u) * 4u;
    const uint32_t aDstOff = t0 * 512u + ((uint32_t)tid & 31u) * 16u;

    const char* bSrcB = (const char*)gB +
        (size_t)((((uint32_t)nb * 4u + ((uint32_t)tid >> 7)) * 256u +
                  (((uint32_t)tid >> 5) & 3u)) * 128u + ((uint32_t)tid & 31u) * 4u) * 4u;
    const uint32_t bDstOff = 16384u + ((uint32_t)tid >> 7) * 2048u +
                             (((uint32_t)tid >> 5) & 3u) * 512u +
                             ((uint32_t)tid & 31u) * 16u;

#define ISSUE(BUF_)                                                           \
    do {                                                                      \
        const uint32_t da_ = sb + (BUF_) * 32768u + aDstOff;                  \
        const uint32_t db_ = sb + (BUF_) * 32768u + bDstOff;                  \
        cpa16(da_,          aSrcB);                                           \
        cpa16(da_ + 4096u,  aSrcB + 262144);                                  \
        cpa16(da_ + 8192u,  aSrcB + 524288);                                  \
        cpa16(da_ + 12288u, aSrcB + 786432);                                  \
        cpa16(db_,          bSrcB);                                           \
        cpa16(db_ + 4096u,  bSrcB + 262144);                                  \
        cpa16(db_ + 8192u,  bSrcB + 16777216);                                \
        cpa16(db_ + 12288u, bSrcB + 17039360);                                \
        asm volatile("cp.async.commit_group;" ::: "memory");                  \
        aSrcB += 2048;                                                        \
        bSrcB += 2048;                                                        \
    } while (0)

    float acc[4][2][2][4];
#pragma unroll
    for (int g = 0; g < 4; g++)
#pragma unroll
        for (int mt = 0; mt < 2; mt++)
#pragma unroll
            for (int nt = 0; nt < 2; nt++)
#pragma unroll
                for (int e = 0; e < 4; e++) acc[g][mt][nt][e] = 0.0f;

#define MMA_BLOCK(BUF_)                                                       \
    do {                                                                      \
        const uint32_t* Ap_ = smw + (BUF_) * STAGE_WORDS + warpM * 1024 + lid * 4; \
        const uint32_t* Bp_ = smw + (BUF_) * STAGE_WORDS + 4096 + warpN * 1024 + lid * 4; \
        _Pragma("unroll")                                                     \
        for (int ks_ = 0; ks_ < 4; ks_++) {                                   \
            const uint4 a0_ = *reinterpret_cast<const uint4*>(Ap_ + ks_ * 128);       \
            const uint4 a1_ = *reinterpret_cast<const uint4*>(Ap_ + 512 + ks_ * 128); \
            _Pragma("unroll")                                                 \
            for (int nt_ = 0; nt_ < 2; nt_++) {                               \
                const uint4 b01_ = *reinterpret_cast<const uint4*>(           \
                    Bp_ + nt_ * 512 + ks_ * 128);                             \
                const uint4 b23_ = *reinterpret_cast<const uint4*>(           \
                    Bp_ + 2048 + nt_ * 512 + ks_ * 128);                      \
                mma8(acc[0][0][nt_], a0_.x, a0_.y, a0_.z, a0_.w, b01_.x, b01_.y); \
                mma8(acc[0][1][nt_], a1_.x, a1_.y, a1_.z, a1_.w, b01_.x, b01_.y); \
                mma8(acc[1][0][nt_], a0_.x, a0_.y, a0_.z, a0_.w, b01_.z, b01_.w); \
                mma8(acc[1][1][nt_], a1_.x, a1_.y, a1_.z, a1_.w, b01_.z, b01_.w); \
                mma8(acc[2][0][nt_], a0_.x, a0_.y, a0_.z, a0_.w, b23_.x, b23_.y); \
                mma8(acc[2][1][nt_], a1_.x, a1_.y, a1_.z, a1_.w, b23_.x, b23_.y); \
                mma8(acc[3][0][nt_], a0_.x, a0_.y, a0_.z, a0_.w, b23_.z, b23_.w); \
                mma8(acc[3][1][nt_], a1_.x, a1_.y, a1_.z, a1_.w, b23_.z, b23_.w); \
            }                                                                 \
        }                                                                     \
    } while (0)

#define WAIT1() asm volatile("cp.async.wait_group 1;" ::: "memory")
#define WAIT0() asm volatile("cp.async.wait_group 0;" ::: "memory")

    ISSUE(0);
    ISSUE(1);

    const int mblk = mb * 128;
    const int nblk = nb * 32;

    for (int su = 0; su < 21; su++) {
        WAIT1(); __syncthreads();
        MMA_BLOCK(0);
        ISSUE(2);
        WAIT1(); __syncthreads();
        MMA_BLOCK(1);
        ISSUE(0);
        WAIT1(); __syncthreads();
        MMA_BLOCK(2);
        if (su < 20) {
            ISSUE(1);
        } else {
            // ---- c-tile prefetch into retired buf1 (overlaps tail MMA) ----
            // 1024 chunks of 16B: chunk q = tid*4+i, row = q>>3, col4 = q&7.
#pragma unroll
            for (int i = 0; i < 4; i++) {
                const uint32_t q = (uint32_t)tid * 4u + i;
                const uint32_t row = q >> 3, c4 = q & 7u;
                cpa16(sb + (CBUF_BASE + row * CROW + c4 * 4u) * 4u,
                      &c[(size_t)(mblk + row) * HDIM + nblk + c4 * 4u]);
            }
            asm volatile("cp.async.commit_group;" ::: "memory");
        }
    }
    WAIT0(); __syncthreads();
    MMA_BLOCK(0);

    // ---- fused LSTM epilogue (MUFU, c from smem) ----
    const int gid = lid >> 2;
    const int tig = lid & 3;
    const float* bias_s = (const float*)(smw + 3 * STAGE_WORDS);
    const float* cbuf = (const float*)(smw + CBUF_BASE);
    float* outH = out;
    float* outC = out + (size_t)BATCH * HDIM;

#pragma unroll
    for (int nt = 0; nt < 2; nt++) {
        const int colloc = warpN * 16 + nt * 8 + tig * 2;
        const float bF0 = bias_s[0 * 32 + colloc], bF1 = bias_s[0 * 32 + colloc + 1];
        const float bI0 = bias_s[1 * 32 + colloc], bI1 = bias_s[1 * 32 + colloc + 1];
        const float bG0 = bias_s[2 * 32 + colloc], bG1 = bias_s[2 * 32 + colloc + 1];
        const float bO0 = bias_s[3 * 32 + colloc], bO1 = bias_s[3 * 32 + colloc + 1];
#pragma unroll
        for (int mt = 0; mt < 2; mt++)
#pragma unroll
            for (int p = 0; p < 2; p++) {
                const int mloc = warpM * 32 + mt * 16 + gid + 8 * p;
                const size_t base = (size_t)(mblk + mloc) * HDIM + nblk + colloc;
                const float2 cc = *(const float2*)&cbuf[mloc * CROW + colloc];
                const int e = p * 2;
                const float pf0 = acc[0][mt][nt][e] + bF0, pf1 = acc[0][mt][nt][e + 1] + bF1;
                const float pi0 = acc[1][mt][nt][e] + bI0, pi1 = acc[1][mt][nt][e + 1] + bI1;
                const float pg0 = acc[2][mt][nt][e] + bG0, pg1 = acc[2][mt][nt][e + 1] + bG1;
                const float po0 = acc[3][mt][nt][e] + bO0, po1 = acc[3][mt][nt][e + 1] + bO1;
                const float f0 = sig_ap(pf0), f1 = sig_ap(pf1);
                const float i0 = sig_ap(pi0), i1 = sig_ap(pi1);
                const float g0 = tanh_ap(pg0), g1 = tanh_ap(pg1);
                const float o0 = sig_ap(po0), o1 = sig_ap(po1);
                const float cn0 = fmaf(f0, cc.x, i0 * g0);
                const float cn1 = fmaf(f1, cc.y, i1 * g1);
                *(float2*)&outH[base] = make_float2(o0 * tanh_ap(cn0), o1 * tanh_ap(cn1));
                *(float2*)&outC[base] = make_float2(cn0, cn1);
            }
    }
}

extern "C" void kernel_launch(void* const* d_in, const int* in_sizes, int n_in,
                              void* d_out, int out_size)
{
    const float* x    = (const float*)d_in[0];
    const float* h    = (const float*)d_in[1];
    const float* c    = (const float*)d_in[2];
    const float* wf_i = (const float*)d_in[3];
    const float* bf_i = (const float*)d_in[4];
    const float* wf_h = (const float*)d_in[5];
    const float* bf_h = (const float*)d_in[6];
    const float* wi_i = (const float*)d_in[7];
    const float* bi_i = (const float*)d_in[8];
    const float* wi_h = (const float*)d_in[9];
    const float* bi_h = (const float*)d_in[10];
    const float* wg_i = (const float*)d_in[11];
    const float* bg_i = (const float*)d_in[12];
    const float* wg_h = (const float*)d_in[13];
    const float* bg_h = (const float*)d_in[14];
    const float* wo_i = (const float*)d_in[15];
    const float* bo_i = (const float*)d_in[16];
    const float* wo_h = (const float*)d_in[17];
    const float* bo_h = (const float*)d_in[18];
    float* out = (float*)d_out;

    cudaFuncSetAttribute(lstm_main, cudaFuncAttributeMaxDynamicSharedMemorySize, SMEM_BYTES);

    prep_kernel<<<24576, 256>>>(x, h, wf_i, wf_h, wi_i, wi_h, wg_i, wg_h, wo_i, wo_h);

    dim3 grid(HDIM / 32, BATCH / 128);   // (32, 64)
    lstm_main<<<grid, 256, SMEM_BYTES>>>(c,
                                         bf_i, bf_h, bi_i, bi_h,
                                         bg_i, bg_h, bo_i, bo_h,
                                         out);
}